// round 10
// baseline (speedup 1.0000x reference)
#include <cuda_runtime.h>

// Attn_Pred_Model: out[slice][s][b] =
//   ( sum_{i=0..7} alpha*beta^i * x[slice][s-1-i][b] + pb_fwd[b]
//     + pb_bwd[((s>>6)-b) & 63] ) * mask(s,b)
// mask(s,b) = 1 iff s >= max(128, 64*(b+1))  (band-constant, band = 64 rows)
//
// R9: single-wave DOUBLE-residency config. CHUNK=128 -> grid=2048 blocks
// (13.8/SM offered). __launch_bounds__(128,14) caps regs at 36 so all 14
// blocks/SM are co-resident: ~55 warps/SM in ONE wave (R3's identical grid
// failed only because 56 regs allowed 9 blocks -> 1.54 waves).
// Register diet: Horner in beta (no coeff array), float2 window (16 regs),
// band-hoisted biases. Per-lane predicated loads still skip the mask-dead
// triangle (~49% of read bytes). Reads ~140MB, writes 256MB.

#define S_DIM   4096
#define B_DIM   64
#define SLICES  256
#define PAST    8
#define CHUNK   128              // rows per thread
#define N_CHUNK (S_DIM / CHUNK)  // 32

__global__ __launch_bounds__(128, 14)
void attn_pred_kernel(const float* __restrict__ x,
                      const float* __restrict__ pb_fwd,
                      const float* __restrict__ pb_bwd,
                      const float* __restrict__ alpha_p,
                      const float* __restrict__ beta_p,
                      float* __restrict__ out)
{
    const int t     = blockIdx.x * blockDim.x + threadIdx.x;
    const int tb    = t & 31;        // float2 lane: columns b0=2*tb, b1=2*tb+1
    const int rest  = t >> 5;
    const int chunk = rest & (N_CHUNK - 1);
    const int slice = rest >> 5;     // rest / N_CHUNK

    const float alpha = alpha_p[0];
    const float beta  = beta_p[0];

    const int b0 = 2 * tb;
    const int b1 = b0 + 1;

    // first active band per column: active iff band q >= qact
    const int qact0 = (b0 + 1 < 2) ? 2 : (b0 + 1);   // max(2, b0+1)
    const int qact1 = b1 + 1;                        // b1 >= 1 so already >= 2
    // x[s] feeds out[s+1..s+8]; col b0 activates first in this pair
    const int ld_thresh = (qact0 << 6) - 8;          // always >= 120 > 0

    const size_t slice_off = (size_t)slice * S_DIM * (B_DIM / 2); // float2 units
    const float2* __restrict__ xin  = (const float2*)x  + slice_off + tb;
    float2*       __restrict__ xout = (float2*)out      + slice_off + tb;

    const int s0 = chunk * CHUNK;

    // rolling window: w[i] = x[s-1-i] for current s (= s0 at start)
    float2 w[PAST];
    #pragma unroll
    for (int i = 0; i < PAST; i++) {
        const int sr = s0 - 1 - i;
        w[i] = (sr >= ld_thresh) ? xin[(size_t)sr * 32]
                                 : make_float2(0.f, 0.f);
    }

    #pragma unroll
    for (int band = 0; band < CHUNK / 64; band++) {
        const int q = (s0 >> 6) + band;          // bucket row, constant in band
        const float bias0 = __ldg(&pb_fwd[b0]) + __ldg(&pb_bwd[(q - b0) & 63]);
        const float bias1 = __ldg(&pb_fwd[b1]) + __ldg(&pb_bwd[(q - b1) & 63]);
        const float m0 = (q >= qact0) ? 1.f : 0.f;
        const float m1 = (q >= qact1) ? 1.f : 0.f;
        const int sbase = q * 64;

        #pragma unroll 8   // depth == PAST so window shift is free register rotation
        for (int r = 0; r < 64; r++) {
            const int s = sbase + r;
            // predicated load: dead-triangle lanes fetch nothing from DRAM
            const float2 cur = (s >= ld_thresh) ? xin[(size_t)s * 32]
                                                : make_float2(0.f, 0.f);

            // Horner: h = w0 + beta*(w1 + beta*(... + beta*w7))
            float hx = w[PAST - 1].x, hy = w[PAST - 1].y;
            #pragma unroll
            for (int i = PAST - 2; i >= 0; i--) {
                hx = fmaf(beta, hx, w[i].x);
                hy = fmaf(beta, hy, w[i].y);
            }

            float2 o;
            o.x = m0 * fmaf(alpha, hx, bias0);
            o.y = m1 * fmaf(alpha, hy, bias1);
            xout[(size_t)s * 32] = o;

            #pragma unroll
            for (int i = PAST - 1; i > 0; i--) w[i] = w[i - 1];
            w[0] = cur;
        }
    }
}

extern "C" void kernel_launch(void* const* d_in, const int* in_sizes, int n_in,
                              void* d_out, int out_size)
{
    // metadata order: x, pb_fwd, pb_bwd, alpha, beta, arange2, mask
    const float* x      = (const float*)d_in[0];
    const float* pb_fwd = (const float*)d_in[1];
    const float* pb_bwd = (const float*)d_in[2];
    const float* alpha  = (const float*)d_in[3];
    const float* beta   = (const float*)d_in[4];
    // arange2 (d_in[5]) and mask (d_in[6]) are reproduced analytically in-kernel.

    const int total_threads = SLICES * N_CHUNK * 32;  // 262144
    const int block = 128;
    attn_pred_kernel<<<total_threads / block, block>>>(
        x, pb_fwd, pb_bwd, alpha, beta, (float*)d_out);
}

// round 11
// speedup vs baseline: 1.3242x; 1.3242x over previous
#include <cuda_runtime.h>

// Attn_Pred_Model: out[slice][s][b] =
//   ( sum_{i=0..7} alpha*beta^i * x[slice][s-1-i][b] + pb_fwd[b]
//     + pb_bwd[((s>>6)-b) & 63] ) * mask(s,b)
// mask(s,b) = 1 iff s >= max(128, 64*(b+1))  (band-constant, band = 64 rows)
//
// Confirmed-best geometry (R2): CHUNK=256 / grid=1024 / 128 thr, float2
// lanes, single full-residency wave, per-lane predicated loads skipping the
// mask-dead triangle (~49% of read bytes), plain LDG/STG.
// R10 delta: row-loop unroll 8 -> 16. The 16 loads in the unrolled body are
// independent; ptxas can front-batch 16 LDGs/warp (2x in-flight read bytes).
// ~72 regs -> 7 blocks/SM >= 6.9 offered keeps the single wave.
// Closed axes (measured): occupancy (R3 waves, R9 spills), cache hints
// (R4 -2%), float4 (R8 -21%), explicit batching (R4 neutral).

#define S_DIM   4096
#define B_DIM   64
#define SLICES  256
#define PAST    8
#define CHUNK   256              // rows per thread
#define N_CHUNK (S_DIM / CHUNK)  // 16

__global__ __launch_bounds__(128)
void attn_pred_kernel(const float* __restrict__ x,
                      const float* __restrict__ pb_fwd,
                      const float* __restrict__ pb_bwd,
                      const float* __restrict__ alpha_p,
                      const float* __restrict__ beta_p,
                      float* __restrict__ out)
{
    const int t     = blockIdx.x * blockDim.x + threadIdx.x;
    const int tb    = t & 31;        // float2 lane: columns b0=2*tb, b1=2*tb+1
    const int rest  = t >> 5;
    const int chunk = rest & (N_CHUNK - 1);
    const int slice = rest >> 4;     // rest / N_CHUNK

    // decay coefficients c[i] = alpha * beta^i
    const float alpha = alpha_p[0];
    const float beta  = beta_p[0];
    float c[PAST];
    {
        float cv = alpha;
        #pragma unroll
        for (int i = 0; i < PAST; i++) { c[i] = cv; cv *= beta; }
    }

    const int b0 = 2 * tb;
    const int b1 = b0 + 1;
    const float pf0 = __ldg(&pb_fwd[b0]);
    const float pf1 = __ldg(&pb_fwd[b1]);

    // first active band per column: active iff s >= 64*qact
    const int qact0 = (b0 + 1 < 2) ? 2 : (b0 + 1);   // max(2, b0+1)
    const int qact1 = b1 + 1;                        // b1 >= 1 so already >= 2
    // load needed iff s + 8 >= 64*qact0  (x[s] feeds out[s+1..s+8]; col b1
    // activates later than b0, so b0's predicate covers the float2 pair)
    const int ld_thresh = (qact0 << 6) - 8;

    const size_t slice_off = (size_t)slice * S_DIM * (B_DIM / 2); // float2 units
    const float2* __restrict__ xin  = (const float2*)x  + slice_off + tb;
    float2*       __restrict__ xout = (float2*)out      + slice_off + tb;

    const int s0 = chunk * CHUNK;

    // rolling window: w[i] = x[s-1-i] for current s (= s0 at start)
    float2 w[PAST];
    #pragma unroll
    for (int i = 0; i < PAST; i++) {
        const int sr = s0 - 1 - i;
        w[i] = (sr >= 0 && sr >= ld_thresh) ? xin[(size_t)sr * 32]
                                            : make_float2(0.f, 0.f);
    }

    #pragma unroll
    for (int band = 0; band < CHUNK / 64; band++) {
        const int q = (s0 >> 6) + band;          // bucket row index, constant in band
        const float bias0 = pf0 + __ldg(&pb_bwd[(q - b0) & 63]);
        const float bias1 = pf1 + __ldg(&pb_bwd[(q - b1) & 63]);
        const float m0 = (q >= qact0) ? 1.f : 0.f;
        const float m1 = (q >= qact1) ? 1.f : 0.f;
        const int sbase = q * 64;

        #pragma unroll 16  // 16 independent loads per body -> deeper LDG batch;
        for (int r = 0; r < 64; r++) {          // multiple of PAST keeps the
            const int s = sbase + r;            // window shift register-rotated
            // predicated load: skipped lanes fetch nothing from DRAM
            const float2 cur = (s >= ld_thresh) ? xin[(size_t)s * 32]
                                                : make_float2(0.f, 0.f);

            float ax = 0.f, ay = 0.f;
            #pragma unroll
            for (int i = 0; i < PAST; i++) {
                ax = fmaf(c[i], w[i].x, ax);
                ay = fmaf(c[i], w[i].y, ay);
            }

            float2 o;
            o.x = m0 * (ax + bias0);
            o.y = m1 * (ay + bias1);
            xout[(size_t)s * 32] = o;

            #pragma unroll
            for (int i = PAST - 1; i > 0; i--) w[i] = w[i - 1];
            w[0] = cur;
        }
    }
}

extern "C" void kernel_launch(void* const* d_in, const int* in_sizes, int n_in,
                              void* d_out, int out_size)
{
    // metadata order: x, pb_fwd, pb_bwd, alpha, beta, arange2, mask
    const float* x      = (const float*)d_in[0];
    const float* pb_fwd = (const float*)d_in[1];
    const float* pb_bwd = (const float*)d_in[2];
    const float* alpha  = (const float*)d_in[3];
    const float* beta   = (const float*)d_in[4];
    // arange2 (d_in[5]) and mask (d_in[6]) are reproduced analytically in-kernel.

    const int total_threads = SLICES * N_CHUNK * 32;  // 131072
    const int block = 128;
    attn_pred_kernel<<<total_threads / block, block>>>(
        x, pb_fwd, pb_bwd, alpha, beta, (float*)d_out);
}